// round 1
// baseline (speedup 1.0000x reference)
#include <cuda_runtime.h>
#include <math.h>

#define EMAX   250000
#define DEDGE  128
#define DTRI   64
#define NBV    8

static __device__ __align__(16) float g_R  [EMAX * DEDGE];
static __device__ __align__(16) float g_M1 [EMAX * DEDGE];
static __device__ __align__(16) float g_T  [EMAX * DTRI];
static __device__ __align__(16) float g_X  [EMAX * DTRI];
static __device__ __align__(16) float g_Y  [EMAX * DEDGE];
static __device__ __align__(16) float g_XST[EMAX * DEDGE];
static __device__ __align__(16) float g_Z  [EMAX * DEDGE];

#define INV_SQRT_2  0.70710678118654752440f
#define INV_SQRT_NB 0.35355339059327376220f

__device__ __forceinline__ float silu_f(float x) {
    return x / (1.0f + __expf(-x));
}

#define EPI_NONE 0
#define EPI_SILU 1
#define EPI_SILU_MUL 2

// C[M x N] = epilogue( A[M x K] @ W[K x N] ), W fully resident in smem.
// Block: 256 threads, 128 rows x N cols, thread tile 8 x (N/16).
template<int K, int N, int EPI>
__global__ void __launch_bounds__(256, 2)
gemm_fused(const float* __restrict__ A, const float* __restrict__ W,
           const float* __restrict__ Rm, float* __restrict__ out, int M)
{
    constexpr int TN = N / 16;
    extern __shared__ float smem[];
    float* Ws = smem;           // K*N floats
    float* At = smem + K * N;   // 16*128 floats (A tile, transposed [k][row])

    const int tid  = threadIdx.x;
    const int trow = tid >> 4;      // 0..15
    const int tcol = tid & 15;      // 0..15
    const int blockRow = blockIdx.x * 128;

    // Load full weight matrix into smem (coalesced float4)
    for (int i = tid; i < (K * N) / 4; i += 256)
        ((float4*)Ws)[i] = ((const float4*)W)[i];

    float acc[8][TN];
    #pragma unroll
    for (int i = 0; i < 8; i++)
        #pragma unroll
        for (int j = 0; j < TN; j++) acc[i][j] = 0.0f;

    for (int kb = 0; kb < K / 16; kb++) {
        // Load A tile: 128 rows x 16 k, stored transposed At[k][row]
        #pragma unroll
        for (int ld = 0; ld < 2; ld++) {
            int f   = tid + ld * 256;     // float4 index, 0..511
            int row = f >> 2;             // 0..127
            int kq  = f & 3;              // 0..3  (4 floats each)
            int grow = blockRow + row;
            float4 v = make_float4(0.f, 0.f, 0.f, 0.f);
            if (grow < M)
                v = *(const float4*)(A + (size_t)grow * K + kb * 16 + kq * 4);
            At[(kq * 4 + 0) * 128 + row] = v.x;
            At[(kq * 4 + 1) * 128 + row] = v.y;
            At[(kq * 4 + 2) * 128 + row] = v.z;
            At[(kq * 4 + 3) * 128 + row] = v.w;
        }
        __syncthreads();

        #pragma unroll
        for (int kk = 0; kk < 16; kk++) {
            float a[8];
            float4 A0 = *(float4*)(At + kk * 128 + trow * 8);
            float4 A1 = *(float4*)(At + kk * 128 + trow * 8 + 4);
            a[0]=A0.x; a[1]=A0.y; a[2]=A0.z; a[3]=A0.w;
            a[4]=A1.x; a[5]=A1.y; a[6]=A1.z; a[7]=A1.w;
            float b[TN];
            #pragma unroll
            for (int jj = 0; jj < TN; jj += 4) {
                float4 B = *(float4*)(Ws + (kb * 16 + kk) * N + tcol * TN + jj);
                b[jj]=B.x; b[jj+1]=B.y; b[jj+2]=B.z; b[jj+3]=B.w;
            }
            #pragma unroll
            for (int i = 0; i < 8; i++)
                #pragma unroll
                for (int j = 0; j < TN; j++)
                    acc[i][j] = fmaf(a[i], b[j], acc[i][j]);
        }
        __syncthreads();
    }

    // Epilogue + store
    #pragma unroll
    for (int i = 0; i < 8; i++) {
        int grow = blockRow + trow * 8 + i;
        if (grow >= M) continue;
        float v[TN];
        #pragma unroll
        for (int j = 0; j < TN; j++) {
            float x = acc[i][j];
            if (EPI == EPI_SILU || EPI == EPI_SILU_MUL) x = silu_f(x);
            v[j] = x;
        }
        if (EPI == EPI_SILU_MUL) {
            #pragma unroll
            for (int jj = 0; jj < TN; jj += 4) {
                float4 r = *(const float4*)(Rm + (size_t)grow * N + tcol * TN + jj);
                v[jj] *= r.x; v[jj+1] *= r.y; v[jj+2] *= r.z; v[jj+3] *= r.w;
            }
        }
        #pragma unroll
        for (int jj = 0; jj < TN; jj += 4) {
            float4 o; o.x=v[jj]; o.y=v[jj+1]; o.z=v[jj+2]; o.w=v[jj+3];
            *(float4*)(out + (size_t)grow * N + tcol * TN + jj) = o;
        }
    }
}

// Triplet gather: X[e][:] = INV_SQRT_NB * sum_nb T[b1[e,nb]][:] * (cbf[e,nb,:] @ W_cbf)
// One warp per edge. W_cbf column pair held in registers; T gathers L2-resident.
__global__ void __launch_bounds__(256)
triplet_kernel(const float* __restrict__ T, const float* __restrict__ cbf,
               const int* __restrict__ idx_s, const int* __restrict__ basis,
               const float* __restrict__ Wc, float* __restrict__ X, int E)
{
    __shared__ float cb[8][128];
    const int warp = threadIdx.x >> 5;
    const int lane = threadIdx.x & 31;

    float w0[16], w1[16];
    #pragma unroll
    for (int c = 0; c < 16; c++) {
        w0[c] = Wc[c * 64 + lane];
        w1[c] = Wc[c * 64 + 32 + lane];
    }

    const int gw     = blockIdx.x * 8 + warp;
    const int nwarps = gridDim.x * 8;

    for (int e = gw; e < E; e += nwarps) {
        int s = idx_s[e];
        int b1v = 0;
        if (lane < 8) b1v = basis[s * 8 + lane];

        float4 v = *(const float4*)(cbf + (size_t)e * 128 + lane * 4);
        *(float4*)(&cb[warp][lane * 4]) = v;
        __syncwarp();

        int bidx[8];
        #pragma unroll
        for (int nb = 0; nb < 8; nb++)
            bidx[nb] = __shfl_sync(0xffffffffu, b1v, nb);

        // Prefetch all gathered T values (coalesced 256B rows, L2-resident)
        float t0[8], t1[8];
        #pragma unroll
        for (int nb = 0; nb < 8; nb++) {
            t0[nb] = T[(size_t)bidx[nb] * 64 + lane];
            t1[nb] = T[(size_t)bidx[nb] * 64 + 32 + lane];
        }

        float acc0 = 0.f, acc1 = 0.f;
        #pragma unroll
        for (int nb = 0; nb < 8; nb++) {
            float d0 = 0.f, d1 = 0.f;
            #pragma unroll
            for (int c = 0; c < 16; c++) {
                float a = cb[warp][nb * 16 + c];
                d0 = fmaf(a, w0[c], d0);
                d1 = fmaf(a, w1[c], d1);
            }
            acc0 = fmaf(t0[nb], d0, acc0);
            acc1 = fmaf(t1[nb], d1, acc1);
        }
        X[(size_t)e * 64 + lane]      = acc0 * INV_SQRT_NB;
        X[(size_t)e * 64 + 32 + lane] = acc1 * INV_SQRT_NB;
        __syncwarp();
    }
}

// out[e][:] = (XST[e][:] + Z[idx_swap[e]][:]) * INV_SQRT_2
__global__ void __launch_bounds__(256)
final_kernel(const float* __restrict__ XST, const float* __restrict__ Z,
             const int* __restrict__ swp, float* __restrict__ out, int E)
{
    size_t total = (size_t)E * 32;  // float4 units (128 floats / row)
    size_t stride = (size_t)gridDim.x * blockDim.x;
    for (size_t i = (size_t)blockIdx.x * blockDim.x + threadIdx.x; i < total; i += stride) {
        size_t e = i >> 5;
        int    q = (int)(i & 31);
        int    s = swp[e];
        float4 a = ((const float4*)XST)[i];
        float4 b = ((const float4*)Z)[(size_t)s * 32 + q];
        float4 r;
        r.x = (a.x + b.x) * INV_SQRT_2;
        r.y = (a.y + b.y) * INV_SQRT_2;
        r.z = (a.z + b.z) * INV_SQRT_2;
        r.w = (a.w + b.w) * INV_SQRT_2;
        ((float4*)out)[i] = r;
    }
}

extern "C" void kernel_launch(void* const* d_in, const int* in_sizes, int n_in,
                              void* d_out, int out_size)
{
    const float* m_st     = (const float*)d_in[0];
    const float* rbf      = (const float*)d_in[1];
    const float* cbf      = (const float*)d_in[2];
    const int*   idx_s    = (const int*)d_in[3];
    const int*   idx_swap = (const int*)d_in[4];
    const int*   basis    = (const int*)d_in[5];
    const float* W_m_rbf  = (const float*)d_in[6];
    const float* W_rbf    = (const float*)d_in[7];
    const float* W_m_cbf  = (const float*)d_in[8];
    const float* W_cbf    = (const float*)d_in[9];
    const float* W_dir    = (const float*)d_in[10];
    const float* W_st     = (const float*)d_in[11];
    const float* W_ts     = (const float*)d_in[12];
    float* out = (float*)d_out;

    const int E = in_sizes[0] / DEDGE;

    float *pR, *pM1, *pT, *pX, *pY, *pXST, *pZ;
    cudaGetSymbolAddress((void**)&pR,   g_R);
    cudaGetSymbolAddress((void**)&pM1,  g_M1);
    cudaGetSymbolAddress((void**)&pT,   g_T);
    cudaGetSymbolAddress((void**)&pX,   g_X);
    cudaGetSymbolAddress((void**)&pY,   g_Y);
    cudaGetSymbolAddress((void**)&pXST, g_XST);
    cudaGetSymbolAddress((void**)&pZ,   g_Z);

    const int gBlocks = (E + 127) / 128;

    // Shared memory sizes (bytes): K*N weights + 16*128 A-tile
    const int smem_16_128  = (16  * 128 + 2048) * 4;   // 16 KB
    const int smem_128_128 = (128 * 128 + 2048) * 4;   // 72 KB
    const int smem_128_64  = (128 * 64  + 2048) * 4;   // 40 KB
    const int smem_64_128  = (64  * 128 + 2048) * 4;   // 40 KB

    cudaFuncSetAttribute(gemm_fused<128, 128, EPI_SILU_MUL>,
                         cudaFuncAttributeMaxDynamicSharedMemorySize, smem_128_128);
    cudaFuncSetAttribute(gemm_fused<128, 128, EPI_SILU>,
                         cudaFuncAttributeMaxDynamicSharedMemorySize, smem_128_128);

    // K0: R = rbf @ W_rbf
    gemm_fused<16, 128, EPI_NONE><<<gBlocks, 256, smem_16_128>>>(rbf, W_rbf, nullptr, pR, E);
    // K1: M1 = silu(m_st @ W_m_rbf) * R
    gemm_fused<128, 128, EPI_SILU_MUL><<<gBlocks, 256, smem_128_128>>>(m_st, W_m_rbf, pR, pM1, E);
    // K2: T = silu(M1 @ W_m_cbf)
    gemm_fused<128, 64, EPI_SILU><<<gBlocks, 256, smem_128_64>>>(pM1, W_m_cbf, nullptr, pT, E);
    // K3: triplet gather -> X
    triplet_kernel<<<2048, 256>>>(pT, cbf, idx_s, basis, W_cbf, pX, E);
    // K4: Y = silu(X @ W_dir)
    gemm_fused<64, 128, EPI_SILU><<<gBlocks, 256, smem_64_128>>>(pX, W_dir, nullptr, pY, E);
    // K5a: XST = silu(Y @ W_st)
    gemm_fused<128, 128, EPI_SILU><<<gBlocks, 256, smem_128_128>>>(pY, W_st, nullptr, pXST, E);
    // K5b: Z = silu(Y @ W_ts)
    gemm_fused<128, 128, EPI_SILU><<<gBlocks, 256, smem_128_128>>>(pY, W_ts, nullptr, pZ, E);
    // K6: out = (XST + Z[idx_swap]) * INV_SQRT_2
    final_kernel<<<4096, 256>>>(pXST, pZ, idx_swap, out, E);
}